// round 1
// baseline (speedup 1.0000x reference)
#include <cuda_runtime.h>
#include <math.h>

// FullCliffordMeanField3DClassifier — collapsed form.
//
// Inputs (metadata order):
//  d_in[0] x  : [1024, 4096, 6] f32
//  d_in[1] W1 : [8, 64]  f32   d_in[2] b1 : [64] f32
//  d_in[3] W2 : [64, 64] f32   d_in[4] b2 : [64] f32
//  d_in[5] W3 : [64, 2]  f32   d_in[6] b3 : [2]  f32
//  out        : [1024, 2] f32
//
// Math: pv = geoprod(pos, vel) has only comps {0:p.v, 4:p1v2-p2v1, 5:p1v3-p3v1, 6:p2v3-p3v2}.
// mean(geoprod(vel, mean_pv)) = geoprod(mean(vel), mean_pv)  (bilinear, mean_pv const per batch).
// Resulting multivector nonzero comps {1,2,3,7}:
//   i1 = V1*m0 - V2*m4 - V3*m5
//   i2 = V2*m0 + V1*m4 - V3*m6
//   i3 = V3*m0 + V1*m5 + V2*m6
//   i7 = V1*m6 - V2*m5 + V3*m4
// Then MLP 8->64->64->2 with exact-erf GELU; only W1 rows {1,2,3,7} contribute.

#define THREADS 256
#define NPTS    4096
#define PAIRS   (NPTS / 2)                 // 2048 pairs of elements (each pair = 3 float4)
#define PPT     (PAIRS / THREADS)          // 8 pairs per thread

__device__ __forceinline__ float gelu_exact(float v) {
    return 0.5f * v * (1.0f + erff(v * 0.70710678118654752440f));
}

__global__ __launch_bounds__(THREADS, 1)
void clifford_meanfield_kernel(
    const float* __restrict__ x,
    const float* __restrict__ W1, const float* __restrict__ b1,
    const float* __restrict__ W2, const float* __restrict__ b2,
    const float* __restrict__ W3, const float* __restrict__ b3,
    float* __restrict__ out)
{
    const int b = blockIdx.x;
    const int t = threadIdx.x;

    const float4* __restrict__ base =
        reinterpret_cast<const float4*>(x + (size_t)b * (size_t)(NPTS * 6));

    float sdot = 0.f, s12 = 0.f, s13 = 0.f, s23 = 0.f;
    float sv1 = 0.f, sv2 = 0.f, sv3 = 0.f;

    #pragma unroll
    for (int k = 0; k < PPT; ++k) {
        const int pi = t + k * THREADS;          // pair index
        const float4 f0 = base[3 * pi + 0];      // p1a p2a p3a v1a
        const float4 f1 = base[3 * pi + 1];      // v2a v3a p1b p2b
        const float4 f2 = base[3 * pi + 2];      // p3b v1b v2b v3b

        // element a
        {
            const float p1 = f0.x, p2 = f0.y, p3 = f0.z;
            const float v1 = f0.w, v2 = f1.x, v3 = f1.y;
            sdot += p1 * v1 + p2 * v2 + p3 * v3;
            s12  += p1 * v2 - p2 * v1;
            s13  += p1 * v3 - p3 * v1;
            s23  += p2 * v3 - p3 * v2;
            sv1 += v1; sv2 += v2; sv3 += v3;
        }
        // element b
        {
            const float p1 = f1.z, p2 = f1.w, p3 = f2.x;
            const float v1 = f2.y, v2 = f2.z, v3 = f2.w;
            sdot += p1 * v1 + p2 * v2 + p3 * v3;
            s12  += p1 * v2 - p2 * v1;
            s13  += p1 * v3 - p3 * v1;
            s23  += p2 * v3 - p3 * v2;
            sv1 += v1; sv2 += v2; sv3 += v3;
        }
    }

    // ---- warp reduction (7 values) ----
    #pragma unroll
    for (int off = 16; off > 0; off >>= 1) {
        sdot += __shfl_xor_sync(0xffffffffu, sdot, off);
        s12  += __shfl_xor_sync(0xffffffffu, s12,  off);
        s13  += __shfl_xor_sync(0xffffffffu, s13,  off);
        s23  += __shfl_xor_sync(0xffffffffu, s23,  off);
        sv1  += __shfl_xor_sync(0xffffffffu, sv1,  off);
        sv2  += __shfl_xor_sync(0xffffffffu, sv2,  off);
        sv3  += __shfl_xor_sync(0xffffffffu, sv3,  off);
    }

    __shared__ float red[8][7];       // 8 warps x 7 sums
    __shared__ float ii[4];           // interaction comps {1,2,3,7}
    __shared__ float h1[64];
    __shared__ float h2[64];

    const int warp = t >> 5;
    const int lane = t & 31;
    if (lane == 0) {
        red[warp][0] = sdot; red[warp][1] = s12; red[warp][2] = s13;
        red[warp][3] = s23;  red[warp][4] = sv1; red[warp][5] = sv2;
        red[warp][6] = sv3;
    }
    __syncthreads();

    if (t == 0) {
        float r[7];
        #pragma unroll
        for (int j = 0; j < 7; ++j) {
            float a = 0.f;
            #pragma unroll
            for (int w = 0; w < 8; ++w) a += red[w][j];
            r[j] = a * (1.0f / (float)NPTS);   // means
        }
        const float m0 = r[0], m4 = r[1], m5 = r[2], m6 = r[3];
        const float V1 = r[4], V2 = r[5], V3 = r[6];
        ii[0] = V1 * m0 - V2 * m4 - V3 * m5;   // e1
        ii[1] = V2 * m0 + V1 * m4 - V3 * m6;   // e2
        ii[2] = V3 * m0 + V1 * m5 + V2 * m6;   // e3
        ii[3] = V1 * m6 - V2 * m5 + V3 * m4;   // e123
    }
    __syncthreads();

    // ---- layer 1: only W1 rows 1,2,3,7 matter ----
    if (t < 64) {
        float a = b1[t];
        a += ii[0] * W1[1 * 64 + t];
        a += ii[1] * W1[2 * 64 + t];
        a += ii[2] * W1[3 * 64 + t];
        a += ii[3] * W1[7 * 64 + t];
        h1[t] = gelu_exact(a);
    }
    __syncthreads();

    // ---- layer 2: 64x64 ----
    if (t < 64) {
        float a = b2[t];
        #pragma unroll
        for (int i = 0; i < 64; ++i) a += h1[i] * W2[i * 64 + t];
        h2[t] = gelu_exact(a);
    }
    __syncthreads();

    // ---- layer 3: 64x2 ----
    if (t < 2) {
        float a = b3[t];
        #pragma unroll
        for (int i = 0; i < 64; ++i) a += h2[i] * W3[i * 2 + t];
        out[b * 2 + t] = a;
    }
}

extern "C" void kernel_launch(void* const* d_in, const int* in_sizes, int n_in,
                              void* d_out, int out_size)
{
    const float* x  = (const float*)d_in[0];
    const float* W1 = (const float*)d_in[1];
    const float* b1 = (const float*)d_in[2];
    const float* W2 = (const float*)d_in[3];
    const float* b2 = (const float*)d_in[4];
    const float* W3 = (const float*)d_in[5];
    const float* b3 = (const float*)d_in[6];
    float* out = (float*)d_out;

    const int B = in_sizes[0] / (NPTS * 6);   // 1024
    clifford_meanfield_kernel<<<B, THREADS>>>(x, W1, b1, W2, b2, W3, b3, out);
}